// round 13
// baseline (speedup 1.0000x reference)
#include <cuda_runtime.h>
#include <cuda_bf16.h>
#include <math_constants.h>
#include <cstdint>

#define NQ        256
#define NK        50000
#define DD        64
#define KT        128
#define NKT       391          // ceil(50000/128)
#define GRID1     148          // persistent CTAs for score kernel
#define GRP       16           // candidate granularity (keys per group)
#define NHG       (NKT * 8)    // 3128 groups
#define OBS_ELEMS 3072
#define CAP       128
#define MARGIN    1.0f         // >> 2x single-bf16 score error bound

// ---- static device scratch ----
__device__ __align__(16) float g_hmin[NQ * NHG];
__device__ int g_topidx[NQ * 8];

// ---- kernel-1 smem (bytes) ----
#define TSTRIDE_B  144
#define SM_Q     0             // 256 x 144 bf16 rows      = 36864
#define SM_K0    36864         // 128 x 144                = 18432
#define SM_K1    55296         //                          = 18432
#define SM_KSQ0  73728         // 128 f32                  = 512
#define SM_KSQ1  74240         //                          = 512
#define SM_ST32  74752         // fp32 k staging 128x256B  = 32768
#define SM_HST   107520        // hmin stage 256x8 f32     = 8192
#define SM_TOTAL 115712

// ============================ helpers ============================
__device__ __forceinline__ uint32_t smem_u32(const void* p) {
    uint32_t a;
    asm("{ .reg .u64 t; cvta.to.shared.u64 t, %1; cvt.u32.u64 %0, t; }" : "=r"(a) : "l"(p));
    return a;
}
__device__ __forceinline__ void ldsm_x4(uint32_t& r0, uint32_t& r1, uint32_t& r2,
                                        uint32_t& r3, uint32_t a) {
    asm volatile("ldmatrix.sync.aligned.m8n8.x4.shared.b16 {%0,%1,%2,%3}, [%4];"
                 : "=r"(r0), "=r"(r1), "=r"(r2), "=r"(r3) : "r"(a));
}
__device__ __forceinline__ void mma_bf16(float& c0, float& c1, float& c2, float& c3,
                                         uint32_t a0, uint32_t a1, uint32_t a2, uint32_t a3,
                                         uint32_t b0, uint32_t b1) {
    asm volatile("mma.sync.aligned.m16n8k16.row.col.f32.bf16.bf16.f32 "
                 "{%0,%1,%2,%3},{%4,%5,%6,%7},{%8,%9},{%0,%1,%2,%3};"
                 : "+f"(c0), "+f"(c1), "+f"(c2), "+f"(c3)
                 : "r"(a0), "r"(a1), "r"(a2), "r"(a3), "r"(b0), "r"(b1));
}
__device__ __forceinline__ void cp_async16(uint32_t dst, const void* src) {
    asm volatile("cp.async.cg.shared.global [%0], [%1], 16;" :: "r"(dst), "l"(src));
}

// convert 32 floats -> bf16 row chunk in smem, accumulate sum of squares
__device__ __forceinline__ void cvt_row_bf16(char* dst, const float4* __restrict__ s,
                                             float& ss) {
    uint2* d = (uint2*)dst;
    #pragma unroll
    for (int i = 0; i < 8; i++) {
        float4 v = s[i];
        ss = fmaf(v.x, v.x, ss); ss = fmaf(v.y, v.y, ss);
        ss = fmaf(v.z, v.z, ss); ss = fmaf(v.w, v.w, ss);
        __nv_bfloat162 p0 = __floats2bfloat162_rn(v.x, v.y);
        __nv_bfloat162 p1 = __floats2bfloat162_rn(v.z, v.w);
        uint2 u;
        u.x = *(uint32_t*)&p0;
        u.y = *(uint32_t*)&p1;
        d[i] = u;
    }
}

// ======================================================================
// Kernel 1: persistent pipelined bf16 GEMM -> per-(query,16-key-group) MIN
// grid 148, 512 threads (16 warps: 8 m-rows x 2 n-cols), 256q x 128k tiles
// ======================================================================
__global__ __launch_bounds__(512, 1) void knn_score_min(
    const float* __restrict__ qm, const float* __restrict__ km)
{
    extern __shared__ char smem[];
    const uint32_t sb = smem_u32(smem);
    const int tid  = threadIdx.x;
    const int wid  = tid >> 5;
    const int lane = tid & 31;
    const int c    = blockIdx.x;
    const int n_it = (c < NKT - 2 * GRID1) ? 3 : 2;   // 95 CTAs do 3, rest 2

    float* stage = (float*)(smem + SM_HST);

    // ---- prologue: load+convert q (all 512 thr) and k tile 'c' (thr<256) ----
    {
        const int row = tid >> 1, hf = tid & 1;
        float dummy = 0.f;
        cvt_row_bf16(smem + SM_Q + row * TSTRIDE_B + hf * 64,
                     (const float4*)(qm + (size_t)row * DD + hf * 32), dummy);
        if (tid < 256) {
            const int j = c * KT + row;   // prologue tiles always in-bounds
            float ss = 0.f;
            cvt_row_bf16(smem + SM_K0 + row * TSTRIDE_B + hf * 64,
                         (const float4*)(km + (size_t)j * DD + hf * 32), ss);
            float tot = ss + __shfl_xor_sync(0xFFFFFFFFu, ss, 1);
            if (hf == 0) ((float*)(smem + SM_KSQ0))[row] = tot;
        }
    }
    __syncthreads();

    const int mrow = wid >> 1;          // 0..7
    const int ncol = wid & 1;           // 0..1
    int p = 0;

    for (int it = 0; it < n_it; it++) {
        const int t = c + it * GRID1;
        const bool have_next = (it + 1 < n_it);

        // ---- prefetch next fp32 k tile via cp.async ----
        if (have_next) {
            const int tn = t + GRID1;
            const int row = tid >> 2, qtr = tid & 3;
            int j = tn * KT + row;
            if (j >= NK) j = NK - 1;
            const char* src = (const char*)(km + (size_t)j * DD) + qtr * 64;
            uint32_t dst = sb + SM_ST32 + row * 256 + qtr * 64;
            #pragma unroll
            for (int i = 0; i < 4; i++)
                cp_async16(dst + i * 16, src + i * 16);
            asm volatile("cp.async.commit_group;" ::: "memory");
        }

        // ---- GEMM from buffer p ----
        const uint32_t kbase = sb + (p ? SM_K1 : SM_K0);
        const float* ksq = (const float*)(smem + (p ? SM_KSQ1 : SM_KSQ0));

        float acc[2][8][4];
        #pragma unroll
        for (int mt = 0; mt < 2; mt++)
            #pragma unroll
            for (int nt = 0; nt < 8; nt++)
                #pragma unroll
                for (int cc = 0; cc < 4; cc++) acc[mt][nt][cc] = 0.f;

        #pragma unroll
        for (int ks16 = 0; ks16 < 4; ks16++) {
            const uint32_t dby = ks16 * 32;
            uint32_t a[2][4];
            #pragma unroll
            for (int mt = 0; mt < 2; mt++) {
                uint32_t addr = sb + SM_Q
                    + (uint32_t)(mrow * 32 + mt * 16 + (lane & 15)) * TSTRIDE_B
                    + dby + ((lane >> 4) << 4);
                ldsm_x4(a[mt][0], a[mt][1], a[mt][2], a[mt][3], addr);
            }
            uint32_t b[8][2];
            #pragma unroll
            for (int np = 0; np < 4; np++) {
                uint32_t n = (uint32_t)(ncol * 64 + np * 16 + ((lane >> 4) << 3) + (lane & 7));
                uint32_t addr = kbase + n * TSTRIDE_B + dby + (((lane >> 3) & 1) << 4);
                ldsm_x4(b[np * 2][0], b[np * 2][1], b[np * 2 + 1][0], b[np * 2 + 1][1], addr);
            }
            #pragma unroll
            for (int mt = 0; mt < 2; mt++)
                #pragma unroll
                for (int nt = 0; nt < 8; nt++)
                    mma_bf16(acc[mt][nt][0], acc[mt][nt][1], acc[mt][nt][2], acc[mt][nt][3],
                             a[mt][0], a[mt][1], a[mt][2], a[mt][3],
                             b[nt][0], b[nt][1]);
        }

        // ---- epilogue: per-(row, 16-col-group) min -> smem stage ----
        {
            const int g = lane >> 2, tq = lane & 3;
            #pragma unroll
            for (int mt = 0; mt < 2; mt++) {
                const int rowb = mrow * 32 + mt * 16 + g;
                #pragma unroll
                for (int gi = 0; gi < 4; gi++) {
                    float m0 = CUDART_INF_F, m1 = CUDART_INF_F;
                    #pragma unroll
                    for (int e = 0; e < 2; e++) {
                        const int nt = gi * 2 + e;
                        const int col = ncol * 64 + nt * 8 + tq * 2;
                        const float kq0 = ksq[col], kq1 = ksq[col + 1];
                        m0 = fminf(m0, fminf(fmaf(-2.f, acc[mt][nt][0], kq0),
                                             fmaf(-2.f, acc[mt][nt][1], kq1)));
                        m1 = fminf(m1, fminf(fmaf(-2.f, acc[mt][nt][2], kq0),
                                             fmaf(-2.f, acc[mt][nt][3], kq1)));
                    }
                    m0 = fminf(m0, __shfl_xor_sync(0xFFFFFFFFu, m0, 1));
                    m0 = fminf(m0, __shfl_xor_sync(0xFFFFFFFFu, m0, 2));
                    m1 = fminf(m1, __shfl_xor_sync(0xFFFFFFFFu, m1, 1));
                    m1 = fminf(m1, __shfl_xor_sync(0xFFFFFFFFu, m1, 2));
                    if (tq == 0) {
                        const int gg = ncol * 4 + gi;
                        stage[rowb * 8 + gg]       = m0;
                        stage[(rowb + 8) * 8 + gg] = m1;
                    }
                }
            }
        }
        __syncthreads();

        // ---- coalesced write-out of this tile's group mins ----
        {
            const int row = tid >> 1, half = tid & 1;
            float4 v = *(float4*)&stage[row * 8 + half * 4];
            *(float4*)&g_hmin[(size_t)row * NHG + t * 8 + half * 4] = v;
        }

        // ---- convert prefetched fp32 -> bf16 buffer 1-p, ksq ----
        if (have_next) {
            asm volatile("cp.async.wait_group 0;" ::: "memory");
            __syncthreads();
            const int row = tid >> 2, qtr = tid & 3;
            const int j = (t + GRID1) * KT + row;
            const float4* s = (const float4*)(smem + SM_ST32 + row * 256 + qtr * 64);
            char* dst = smem + (p ? SM_K0 : SM_K1) + row * TSTRIDE_B + qtr * 32;
            float ss = 0.f;
            uint2* d = (uint2*)dst;
            #pragma unroll
            for (int i = 0; i < 4; i++) {
                float4 v = s[i];
                ss = fmaf(v.x, v.x, ss); ss = fmaf(v.y, v.y, ss);
                ss = fmaf(v.z, v.z, ss); ss = fmaf(v.w, v.w, ss);
                __nv_bfloat162 p0 = __floats2bfloat162_rn(v.x, v.y);
                __nv_bfloat162 p1 = __floats2bfloat162_rn(v.z, v.w);
                uint2 u;
                u.x = *(uint32_t*)&p0;
                u.y = *(uint32_t*)&p1;
                d[i] = u;
            }
            ss += __shfl_xor_sync(0xFFFFFFFFu, ss, 1);
            ss += __shfl_xor_sync(0xFFFFFFFFu, ss, 2);
            if (qtr == 0)
                ((float*)(smem + (p ? SM_KSQ0 : SM_KSQ1)))[row] =
                    (j < NK) ? ss : CUDART_INF_F;
        }
        __syncthreads();
        p ^= 1;
    }
}

// ======================================================================
// Kernel 2: exact-8th cutoff -> compact -> exact fp32 rescore -> top-8.
// grid NQ, 512 threads. (Round-10 algorithm, widened block.)
// ======================================================================
#define INS8T(s_, j_)                                                            \
    if ((s_) < l[7] || ((s_) == l[7] && (j_) < li[7])) {                         \
        l[7] = (s_); li[7] = (j_);                                               \
        _Pragma("unroll")                                                        \
        for (int u = 7; u > 0; u--)                                              \
            if (l[u] < l[u-1] || (l[u] == l[u-1] && li[u] < li[u-1])) {          \
                float ts = l[u]; l[u] = l[u-1]; l[u-1] = ts;                     \
                int ti = li[u]; li[u] = li[u-1]; li[u-1] = ti; }                 \
    }

#define INS1(s_)                                                                 \
    if ((s_) < l[7]) {                                                           \
        l[7] = (s_);                                                             \
        _Pragma("unroll")                                                        \
        for (int u = 7; u > 0; u--)                                              \
            if (l[u] < l[u-1]) { float ts = l[u]; l[u] = l[u-1]; l[u-1] = ts; }  \
    }

__global__ __launch_bounds__(512) void knn_select(
    const float* __restrict__ qm, const float* __restrict__ km)
{
    __shared__ float qs[64];
    __shared__ float ms[512 * 8];
    __shared__ int   mi[512 * 8];
    __shared__ int   s_list[CAP];
    __shared__ int   s_cnt;
    __shared__ float s_cut;
    const int q = blockIdx.x, tid = threadIdx.x;

    if (tid < 64) qs[tid] = qm[(size_t)q * DD + tid];
    if (tid == 0) s_cnt = 0;

    const float* hrow = &g_hmin[(size_t)q * NHG];
    const float4* h4 = (const float4*)hrow;
    const int NV = NHG / 4;   // 782 float4

    // ---- phase A: per-thread top-8 of group-mins (float4 loads) ----
    float l[8];
    #pragma unroll
    for (int i = 0; i < 8; i++) l[i] = CUDART_INF_F;
    #pragma unroll
    for (int r = 0; r < 2; r++) {
        const int v4 = tid + r * 512;
        if (v4 < NV) {
            float4 v = h4[v4];
            INS1(v.x); INS1(v.y); INS1(v.z); INS1(v.w);
        }
    }
    #pragma unroll
    for (int m = 0; m < 8; m++) ms[tid * 8 + m] = l[m];

    for (int st = 256; st >= 1; st >>= 1) {
        __syncthreads();
        if (tid < st) {
            const int o = (tid + st) * 8;
            #pragma unroll 1
            for (int m = 0; m < 8; m++) {
                float s = ms[o + m];
                if (s >= l[7]) break;
                INS1(s);
            }
            #pragma unroll
            for (int m = 0; m < 8; m++) ms[tid * 8 + m] = l[m];
        }
    }
    if (tid == 0) s_cut = l[7] + MARGIN;
    __syncthreads();

    // ---- phase B: compact candidate 16-key groups (float4 loads) ----
    const float cut = s_cut;
    #pragma unroll
    for (int r = 0; r < 2; r++) {
        const int v4 = tid + r * 512;
        if (v4 < NV) {
            float4 v = h4[v4];
            if (v.x <= cut) { int p = atomicAdd(&s_cnt, 1); if (p < CAP) s_list[p] = v4 * 4; }
            if (v.y <= cut) { int p = atomicAdd(&s_cnt, 1); if (p < CAP) s_list[p] = v4 * 4 + 1; }
            if (v.z <= cut) { int p = atomicAdd(&s_cnt, 1); if (p < CAP) s_list[p] = v4 * 4 + 2; }
            if (v.w <= cut) { int p = atomicAdd(&s_cnt, 1); if (p < CAP) s_list[p] = v4 * 4 + 3; }
        }
    }
    __syncthreads();
    const int cnt = (s_cnt < CAP) ? s_cnt : CAP;

    // ---- phase C: exact fp32 rescore of cnt*16 keys ----
    int li[8];
    #pragma unroll
    for (int i = 0; i < 8; i++) { l[i] = CUDART_INF_F; li[i] = 0x7FFFFFFF; }

    const float4* qp = (const float4*)qs;
    for (int u = tid; u < cnt * GRP; u += 512) {
        const int j = s_list[u >> 4] * GRP + (u & 15);
        if (j < NK) {
            const float4* kp = (const float4*)(km + (size_t)j * DD);
            float dot = 0.f, ks = 0.f;
            #pragma unroll
            for (int w = 0; w < 16; w++) {
                float4 kv = kp[w];
                float4 qv = qp[w];
                dot = fmaf(kv.x, qv.x, dot); ks = fmaf(kv.x, kv.x, ks);
                dot = fmaf(kv.y, qv.y, dot); ks = fmaf(kv.y, kv.y, ks);
                dot = fmaf(kv.z, qv.z, dot); ks = fmaf(kv.z, kv.z, ks);
                dot = fmaf(kv.w, qv.w, dot); ks = fmaf(kv.w, kv.w, ks);
            }
            float s = fmaf(-2.f, dot, ks);
            INS8T(s, j);
        }
    }
    #pragma unroll
    for (int m = 0; m < 8; m++) { ms[tid * 8 + m] = l[m]; mi[tid * 8 + m] = li[m]; }

    for (int st = 256; st >= 1; st >>= 1) {
        __syncthreads();
        if (tid < st) {
            const int o = (tid + st) * 8;
            #pragma unroll 1
            for (int m = 0; m < 8; m++) {
                float s = ms[o + m];
                int   j = mi[o + m];
                bool better = (s < l[7]) || (s == l[7] && j < li[7]);
                if (!better) break;
                l[7] = s; li[7] = j;
                #pragma unroll
                for (int u = 7; u > 0; u--)
                    if (l[u] < l[u-1] || (l[u] == l[u-1] && li[u] < li[u-1])) {
                        float ts = l[u]; l[u] = l[u-1]; l[u-1] = ts;
                        int ti = li[u]; li[u] = li[u-1]; li[u-1] = ti;
                    }
            }
            #pragma unroll
            for (int m = 0; m < 8; m++) { ms[tid * 8 + m] = l[m]; mi[tid * 8 + m] = li[m]; }
        }
    }
    if (tid == 0) {
        #pragma unroll
        for (int m = 0; m < 8; m++) g_topidx[q * 8 + m] = li[m];
    }
}

// ======================================================================
// Kernel 3: gather obs[idx] -> out [8, 256, 3072]
// 2048 blocks x 128 threads, 6 independent float4 copies per thread
// ======================================================================
__global__ __launch_bounds__(128) void knn_gather_kernel(
    const float* __restrict__ obs, float* __restrict__ out)
{
    const int b  = blockIdx.x;
    const int kk = b >> 8;
    const int q  = b & 255;
    const int src = g_topidx[q * 8 + kk];
    const int tid = threadIdx.x;

    const float4* s = (const float4*)(obs + (size_t)src * OBS_ELEMS);
    float4*       d = (float4*)(out + ((size_t)kk * NQ + q) * OBS_ELEMS);

    float4 v0 = s[tid];
    float4 v1 = s[tid + 128];
    float4 v2 = s[tid + 256];
    float4 v3 = s[tid + 384];
    float4 v4 = s[tid + 512];
    float4 v5 = s[tid + 640];
    d[tid]       = v0;
    d[tid + 128] = v1;
    d[tid + 256] = v2;
    d[tid + 384] = v3;
    d[tid + 512] = v4;
    d[tid + 640] = v5;
}

// ======================================================================
extern "C" void kernel_launch(void* const* d_in, const int* in_sizes, int n_in,
                              void* d_out, int out_size)
{
    const float* q   = (const float*)d_in[0];
    const float* k   = (const float*)d_in[1];
    const float* obs = (const float*)d_in[2];
    float* out = (float*)d_out;

    cudaFuncSetAttribute(knn_score_min,
                         cudaFuncAttributeMaxDynamicSharedMemorySize, SM_TOTAL);

    knn_score_min<<<GRID1, 512, SM_TOTAL>>>(q, k);
    knn_select<<<NQ, 512>>>(q, k);
    knn_gather_kernel<<<NQ * 8, 128>>>(obs, out);
}

// round 14
// speedup vs baseline: 1.3853x; 1.3853x over previous
#include <cuda_runtime.h>
#include <cuda_bf16.h>
#include <math_constants.h>
#include <cstdint>

#define NQ        256
#define NK        50000
#define DD        64
#define KT        128
#define NKT       391          // ceil(50000/128)
#define GRID1     148          // persistent CTAs for score kernel
#define GRP       16           // candidate granularity (keys per group)
#define NHG       (NKT * 8)    // 3128 groups (no padding; 3128 % 4 == 0)
#define OBS_ELEMS 3072
#define CAP       128
#define MARGIN    1.0f         // >> 2x single-bf16 score error bound

// ---- static device scratch ----
__device__ __align__(16) float g_hmin[NQ * NHG];
__device__ int   g_topidx[NQ * 8];

// ---- kernel-1 smem (bytes) ----
#define TSTRIDE_B  144
#define SM_Q     0             // 256 x 144 bf16 rows      = 36864
#define SM_K0    36864         // 128 x 144                = 18432
#define SM_K1    55296         //                          = 18432
#define SM_KSQ0  73728         // 128 f32                  = 512
#define SM_KSQ1  74240         //                          = 512
#define SM_ST32  74752         // fp32 k staging 128x256B  = 32768
#define SM_HST   107520        // hmin stage 256x8 f32     = 8192
#define SM_TOTAL 115712

// ============================ helpers ============================
__device__ __forceinline__ uint32_t smem_u32(const void* p) {
    uint32_t a;
    asm("{ .reg .u64 t; cvta.to.shared.u64 t, %1; cvt.u32.u64 %0, t; }" : "=r"(a) : "l"(p));
    return a;
}
__device__ __forceinline__ void ldsm_x4(uint32_t& r0, uint32_t& r1, uint32_t& r2,
                                        uint32_t& r3, uint32_t a) {
    asm volatile("ldmatrix.sync.aligned.m8n8.x4.shared.b16 {%0,%1,%2,%3}, [%4];"
                 : "=r"(r0), "=r"(r1), "=r"(r2), "=r"(r3) : "r"(a));
}
__device__ __forceinline__ void mma_bf16(float& c0, float& c1, float& c2, float& c3,
                                         uint32_t a0, uint32_t a1, uint32_t a2, uint32_t a3,
                                         uint32_t b0, uint32_t b1) {
    asm volatile("mma.sync.aligned.m16n8k16.row.col.f32.bf16.bf16.f32 "
                 "{%0,%1,%2,%3},{%4,%5,%6,%7},{%8,%9},{%0,%1,%2,%3};"
                 : "+f"(c0), "+f"(c1), "+f"(c2), "+f"(c3)
                 : "r"(a0), "r"(a1), "r"(a2), "r"(a3), "r"(b0), "r"(b1));
}
__device__ __forceinline__ void cp_async16(uint32_t dst, const void* src) {
    asm volatile("cp.async.cg.shared.global [%0], [%1], 16;" :: "r"(dst), "l"(src));
}

// convert 32 floats -> bf16 row chunk in smem, accumulate sum of squares
__device__ __forceinline__ void cvt_row_bf16(char* dst, const float4* __restrict__ s,
                                             float& ss) {
    uint2* d = (uint2*)dst;
    #pragma unroll
    for (int i = 0; i < 8; i++) {
        float4 v = s[i];
        ss = fmaf(v.x, v.x, ss); ss = fmaf(v.y, v.y, ss);
        ss = fmaf(v.z, v.z, ss); ss = fmaf(v.w, v.w, ss);
        __nv_bfloat162 p0 = __floats2bfloat162_rn(v.x, v.y);
        __nv_bfloat162 p1 = __floats2bfloat162_rn(v.z, v.w);
        uint2 u;
        u.x = *(uint32_t*)&p0;
        u.y = *(uint32_t*)&p1;
        d[i] = u;
    }
}

// ======================================================================
// Kernel 1: persistent pipelined bf16 GEMM -> per-(query,16-key-group) MIN
// grid 148, 512 threads (16 warps: 8 m-rows x 2 n-cols), 256q x 128k tiles
// ======================================================================
__global__ __launch_bounds__(512, 1) void knn_score_min(
    const float* __restrict__ qm, const float* __restrict__ km)
{
    extern __shared__ char smem[];
    const uint32_t sb = smem_u32(smem);
    const int tid  = threadIdx.x;
    const int wid  = tid >> 5;
    const int lane = tid & 31;
    const int c    = blockIdx.x;
    const int n_it = (c < NKT - 2 * GRID1) ? 3 : 2;   // 95 CTAs do 3, rest 2

    float* stage = (float*)(smem + SM_HST);

    // ---- prologue: load+convert q (all 512 thr) and k tile 'c' (thr<256) ----
    {
        const int row = tid >> 1, hf = tid & 1;
        float dummy = 0.f;
        cvt_row_bf16(smem + SM_Q + row * TSTRIDE_B + hf * 64,
                     (const float4*)(qm + (size_t)row * DD + hf * 32), dummy);
        if (tid < 256) {
            const int j = c * KT + row;   // prologue tiles always in-bounds
            float ss = 0.f;
            cvt_row_bf16(smem + SM_K0 + row * TSTRIDE_B + hf * 64,
                         (const float4*)(km + (size_t)j * DD + hf * 32), ss);
            float tot = ss + __shfl_xor_sync(0xFFFFFFFFu, ss, 1);
            if (hf == 0) ((float*)(smem + SM_KSQ0))[row] = tot;
        }
    }
    __syncthreads();

    const int mrow = wid >> 1;          // 0..7
    const int ncol = wid & 1;           // 0..1
    int p = 0;

    for (int it = 0; it < n_it; it++) {
        const int t = c + it * GRID1;
        const bool have_next = (it + 1 < n_it);

        // ---- prefetch next fp32 k tile via cp.async ----
        if (have_next) {
            const int tn = t + GRID1;
            const int row = tid >> 2, qtr = tid & 3;
            int j = tn * KT + row;
            if (j >= NK) j = NK - 1;
            const char* src = (const char*)(km + (size_t)j * DD) + qtr * 64;
            uint32_t dst = sb + SM_ST32 + row * 256 + qtr * 64;
            #pragma unroll
            for (int i = 0; i < 4; i++)
                cp_async16(dst + i * 16, src + i * 16);
            asm volatile("cp.async.commit_group;" ::: "memory");
        }

        // ---- GEMM from buffer p ----
        const uint32_t kbase = sb + (p ? SM_K1 : SM_K0);
        const float* ksq = (const float*)(smem + (p ? SM_KSQ1 : SM_KSQ0));

        float acc[2][8][4];
        #pragma unroll
        for (int mt = 0; mt < 2; mt++)
            #pragma unroll
            for (int nt = 0; nt < 8; nt++)
                #pragma unroll
                for (int cc = 0; cc < 4; cc++) acc[mt][nt][cc] = 0.f;

        #pragma unroll
        for (int ks16 = 0; ks16 < 4; ks16++) {
            const uint32_t dby = ks16 * 32;
            uint32_t a[2][4];
            #pragma unroll
            for (int mt = 0; mt < 2; mt++) {
                uint32_t addr = sb + SM_Q
                    + (uint32_t)(mrow * 32 + mt * 16 + (lane & 15)) * TSTRIDE_B
                    + dby + ((lane >> 4) << 4);
                ldsm_x4(a[mt][0], a[mt][1], a[mt][2], a[mt][3], addr);
            }
            uint32_t b[8][2];
            #pragma unroll
            for (int np = 0; np < 4; np++) {
                uint32_t n = (uint32_t)(ncol * 64 + np * 16 + ((lane >> 4) << 3) + (lane & 7));
                uint32_t addr = kbase + n * TSTRIDE_B + dby + (((lane >> 3) & 1) << 4);
                ldsm_x4(b[np * 2][0], b[np * 2][1], b[np * 2 + 1][0], b[np * 2 + 1][1], addr);
            }
            #pragma unroll
            for (int mt = 0; mt < 2; mt++)
                #pragma unroll
                for (int nt = 0; nt < 8; nt++)
                    mma_bf16(acc[mt][nt][0], acc[mt][nt][1], acc[mt][nt][2], acc[mt][nt][3],
                             a[mt][0], a[mt][1], a[mt][2], a[mt][3],
                             b[nt][0], b[nt][1]);
        }

        // ---- epilogue: per-(row, 16-col-group) min -> smem stage ----
        {
            const int g = lane >> 2, tq = lane & 3;
            #pragma unroll
            for (int mt = 0; mt < 2; mt++) {
                const int rowb = mrow * 32 + mt * 16 + g;
                #pragma unroll
                for (int gi = 0; gi < 4; gi++) {
                    float m0 = CUDART_INF_F, m1 = CUDART_INF_F;
                    #pragma unroll
                    for (int e = 0; e < 2; e++) {
                        const int nt = gi * 2 + e;
                        const int col = ncol * 64 + nt * 8 + tq * 2;
                        const float kq0 = ksq[col], kq1 = ksq[col + 1];
                        m0 = fminf(m0, fminf(fmaf(-2.f, acc[mt][nt][0], kq0),
                                             fmaf(-2.f, acc[mt][nt][1], kq1)));
                        m1 = fminf(m1, fminf(fmaf(-2.f, acc[mt][nt][2], kq0),
                                             fmaf(-2.f, acc[mt][nt][3], kq1)));
                    }
                    m0 = fminf(m0, __shfl_xor_sync(0xFFFFFFFFu, m0, 1));
                    m0 = fminf(m0, __shfl_xor_sync(0xFFFFFFFFu, m0, 2));
                    m1 = fminf(m1, __shfl_xor_sync(0xFFFFFFFFu, m1, 1));
                    m1 = fminf(m1, __shfl_xor_sync(0xFFFFFFFFu, m1, 2));
                    if (tq == 0) {
                        const int gg = ncol * 4 + gi;
                        stage[rowb * 8 + gg]       = m0;
                        stage[(rowb + 8) * 8 + gg] = m1;
                    }
                }
            }
        }
        __syncthreads();

        // ---- coalesced write-out of this tile's group mins ----
        {
            const int row = tid >> 1, half = tid & 1;
            float4 v = *(float4*)&stage[row * 8 + half * 4];
            *(float4*)&g_hmin[(size_t)row * NHG + t * 8 + half * 4] = v;
        }

        // ---- convert prefetched fp32 -> bf16 buffer 1-p, ksq ----
        if (have_next) {
            asm volatile("cp.async.wait_group 0;" ::: "memory");
            __syncthreads();
            const int row = tid >> 2, qtr = tid & 3;
            const int j = (t + GRID1) * KT + row;
            const float4* s = (const float4*)(smem + SM_ST32 + row * 256 + qtr * 64);
            char* dst = smem + (p ? SM_K0 : SM_K1) + row * TSTRIDE_B + qtr * 32;
            float ss = 0.f;
            uint2* d = (uint2*)dst;
            #pragma unroll
            for (int i = 0; i < 4; i++) {
                float4 v = s[i];
                ss = fmaf(v.x, v.x, ss); ss = fmaf(v.y, v.y, ss);
                ss = fmaf(v.z, v.z, ss); ss = fmaf(v.w, v.w, ss);
                __nv_bfloat162 p0 = __floats2bfloat162_rn(v.x, v.y);
                __nv_bfloat162 p1 = __floats2bfloat162_rn(v.z, v.w);
                uint2 u;
                u.x = *(uint32_t*)&p0;
                u.y = *(uint32_t*)&p1;
                d[i] = u;
            }
            ss += __shfl_xor_sync(0xFFFFFFFFu, ss, 1);
            ss += __shfl_xor_sync(0xFFFFFFFFu, ss, 2);
            if (qtr == 0)
                ((float*)(smem + (p ? SM_KSQ0 : SM_KSQ1)))[row] =
                    (j < NK) ? ss : CUDART_INF_F;
        }
        __syncthreads();
        p ^= 1;
    }
}

// ======================================================================
// Kernel 2 (fused): cutoff from group-mins -> compact -> exact fp32
//                   rescore -> exact top-8. grid NQ, 256 threads.
// ======================================================================
#define INS8T(s_, j_)                                                            \
    if ((s_) < l[7] || ((s_) == l[7] && (j_) < li[7])) {                         \
        l[7] = (s_); li[7] = (j_);                                               \
        _Pragma("unroll")                                                        \
        for (int u = 7; u > 0; u--)                                              \
            if (l[u] < l[u-1] || (l[u] == l[u-1] && li[u] < li[u-1])) {          \
                float ts = l[u]; l[u] = l[u-1]; l[u-1] = ts;                     \
                int ti = li[u]; li[u] = li[u-1]; li[u-1] = ti; }                 \
    }

#define INS1(s_)                                                                 \
    if ((s_) < l[7]) {                                                           \
        l[7] = (s_);                                                             \
        _Pragma("unroll")                                                        \
        for (int u = 7; u > 0; u--)                                              \
            if (l[u] < l[u-1]) { float ts = l[u]; l[u] = l[u-1]; l[u-1] = ts; }  \
    }

__global__ __launch_bounds__(256) void knn_select(
    const float* __restrict__ qm, const float* __restrict__ km)
{
    __shared__ float qs[64];
    __shared__ float ms[256 * 8];
    __shared__ int   mi[256 * 8];
    __shared__ int   s_list[CAP];
    __shared__ int   s_cnt;
    __shared__ float s_cut;
    const int q = blockIdx.x, tid = threadIdx.x;

    if (tid < 64) qs[tid] = qm[(size_t)q * DD + tid];
    if (tid == 0) s_cnt = 0;

    const float4* h4 = (const float4*)&g_hmin[(size_t)q * NHG];
    const int NV = NHG / 4;   // 782 float4

    // ---- phase A: per-thread top-8 of group-mins (float4 loads) ----
    float l[8];
    #pragma unroll
    for (int i = 0; i < 8; i++) l[i] = CUDART_INF_F;
    #pragma unroll
    for (int r = 0; r < 4; r++) {
        const int v4 = tid + r * 256;
        if (v4 < NV) {
            float4 v = h4[v4];
            INS1(v.x); INS1(v.y); INS1(v.z); INS1(v.w);
        }
    }
    #pragma unroll
    for (int m = 0; m < 8; m++) ms[tid * 8 + m] = l[m];

    for (int st = 128; st >= 1; st >>= 1) {
        __syncthreads();
        if (tid < st) {
            const int o = (tid + st) * 8;
            #pragma unroll 1
            for (int m = 0; m < 8; m++) {
                float s = ms[o + m];
                if (s >= l[7]) break;
                INS1(s);
            }
            #pragma unroll
            for (int m = 0; m < 8; m++) ms[tid * 8 + m] = l[m];
        }
    }
    if (tid == 0) s_cut = l[7] + MARGIN;
    __syncthreads();

    // ---- phase B: compact candidate 16-key groups (float4 loads) ----
    const float cut = s_cut;
    #pragma unroll
    for (int r = 0; r < 4; r++) {
        const int v4 = tid + r * 256;
        if (v4 < NV) {
            float4 v = h4[v4];
            if (v.x <= cut) { int p = atomicAdd(&s_cnt, 1); if (p < CAP) s_list[p] = v4 * 4; }
            if (v.y <= cut) { int p = atomicAdd(&s_cnt, 1); if (p < CAP) s_list[p] = v4 * 4 + 1; }
            if (v.z <= cut) { int p = atomicAdd(&s_cnt, 1); if (p < CAP) s_list[p] = v4 * 4 + 2; }
            if (v.w <= cut) { int p = atomicAdd(&s_cnt, 1); if (p < CAP) s_list[p] = v4 * 4 + 3; }
        }
    }
    __syncthreads();
    const int cnt = (s_cnt < CAP) ? s_cnt : CAP;

    // ---- phase C: exact fp32 rescore of cnt*16 keys ----
    int li[8];
    #pragma unroll
    for (int i = 0; i < 8; i++) { l[i] = CUDART_INF_F; li[i] = 0x7FFFFFFF; }

    const float4* qp = (const float4*)qs;
    for (int u = tid; u < cnt * GRP; u += 256) {
        const int j = s_list[u >> 4] * GRP + (u & 15);
        if (j < NK) {
            const float4* kp = (const float4*)(km + (size_t)j * DD);
            float dot = 0.f, ks = 0.f;
            #pragma unroll
            for (int w = 0; w < 16; w++) {
                float4 kv = kp[w];
                float4 qv = qp[w];
                dot = fmaf(kv.x, qv.x, dot); ks = fmaf(kv.x, kv.x, ks);
                dot = fmaf(kv.y, qv.y, dot); ks = fmaf(kv.y, kv.y, ks);
                dot = fmaf(kv.z, qv.z, dot); ks = fmaf(kv.z, kv.z, ks);
                dot = fmaf(kv.w, qv.w, dot); ks = fmaf(kv.w, kv.w, ks);
            }
            float s = fmaf(-2.f, dot, ks);
            INS8T(s, j);
        }
    }
    #pragma unroll
    for (int m = 0; m < 8; m++) { ms[tid * 8 + m] = l[m]; mi[tid * 8 + m] = li[m]; }

    for (int st = 128; st >= 1; st >>= 1) {
        __syncthreads();
        if (tid < st) {
            const int o = (tid + st) * 8;
            #pragma unroll 1
            for (int m = 0; m < 8; m++) {
                float s = ms[o + m];
                int   j = mi[o + m];
                bool better = (s < l[7]) || (s == l[7] && j < li[7]);
                if (!better) break;
                l[7] = s; li[7] = j;
                #pragma unroll
                for (int u = 7; u > 0; u--)
                    if (l[u] < l[u-1] || (l[u] == l[u-1] && li[u] < li[u-1])) {
                        float ts = l[u]; l[u] = l[u-1]; l[u-1] = ts;
                        int ti = li[u]; li[u] = li[u-1]; li[u-1] = ti;
                    }
            }
            #pragma unroll
            for (int m = 0; m < 8; m++) { ms[tid * 8 + m] = l[m]; mi[tid * 8 + m] = li[m]; }
        }
    }
    if (tid == 0) {
        #pragma unroll
        for (int m = 0; m < 8; m++) g_topidx[q * 8 + m] = li[m];
    }
}

// ======================================================================
// Kernel 3: gather obs[idx] -> out [8, 256, 3072]  (2048 blocks, max MLP)
// ======================================================================
__global__ __launch_bounds__(256) void knn_gather_kernel(
    const float* __restrict__ obs, float* __restrict__ out)
{
    const int b  = blockIdx.x;
    const int kk = b >> 8;
    const int q  = b & 255;
    const int src = g_topidx[q * 8 + kk];

    const float4* s = (const float4*)(obs + (size_t)src * OBS_ELEMS);
    float4*       d = (float4*)(out + ((size_t)kk * NQ + q) * OBS_ELEMS);

    #pragma unroll
    for (int i = threadIdx.x; i < OBS_ELEMS / 4; i += 256)
        d[i] = s[i];
}

// ======================================================================
extern "C" void kernel_launch(void* const* d_in, const int* in_sizes, int n_in,
                              void* d_out, int out_size)
{
    const float* q   = (const float*)d_in[0];
    const float* k   = (const float*)d_in[1];
    const float* obs = (const float*)d_in[2];
    float* out = (float*)d_out;

    cudaFuncSetAttribute(knn_score_min,
                         cudaFuncAttributeMaxDynamicSharedMemorySize, SM_TOTAL);

    knn_score_min<<<GRID1, 512, SM_TOTAL>>>(q, k);
    knn_select<<<NQ, 256>>>(q, k);
    knn_gather_kernel<<<NQ * 8, 256>>>(obs, out);
}